// round 9
// baseline (speedup 1.0000x reference)
#include <cuda_runtime.h>
#include <math.h>
#include <stdint.h>

// BackflowNet: B=128, N=64, D=2, H=64, M=64, L=2.
// Stage-batched multi-kernel pipeline: each GEMM stage runs over all
// 524288 (b,i,j) rows at once (4096 CTAs, 12 warps/SM) instead of
// per-batch chained GEMMs at 8 warps/SM. f32x2 FFMA2 mainloop, W in smem,
// A streamed from global, no barriers in hot loops.

__device__ float g_he [128u*64u*64u*64u];   // [b][i][j][m]
__device__ float g_tmp[128u*64u*64u*64u];
__device__ float g_hv [128u*64u*64u];       // [b][j][h]
__device__ float g_pre[128u*64u*64u];       // [b][i][m]
__device__ float g_accp[256u*64u*64u];      // [(b,half)][j][m]

__device__ __forceinline__ float gelu_exact(float x) {
    return 0.5f * x * (1.0f + erff(x * 0.70710678118654752f));
}
__device__ __forceinline__ unsigned long long pk2(float lo, float hi) {
    unsigned long long r;
    asm("mov.b64 %0, {%1, %2};" : "=l"(r) : "f"(lo), "f"(hi));
    return r;
}
__device__ __forceinline__ void upk2(unsigned long long v, float& lo, float& hi) {
    asm("mov.b64 {%0, %1}, %2;" : "=f"(lo), "=f"(hi) : "l"(v));
}
__device__ __forceinline__ void fma2(unsigned long long& d, unsigned long long a, unsigned long long b) {
    asm("fma.rn.f32x2 %0, %1, %2, %0;" : "+l"(d) : "l"(a), "l"(b));
}

#define RANK1(rr, av, wv) \
    rr[0]=fmaf(av, wv.x, rr[0]); rr[1]=fmaf(av, wv.y, rr[1]); \
    rr[2]=fmaf(av, wv.z, rr[2]); rr[3]=fmaf(av, wv.w, rr[3]);
#define TILE4(R, a0v, a1v, a2v, a3v, W) \
    RANK1(R[0], a0v, W) RANK1(R[1], a1v, W) RANK1(R[2], a2v, W) RANK1(R[3], a3v, W)

// scalar 64x64x64 GEMM for per-batch small stages (256 threads)
__device__ __forceinline__ void mm64(
    const float* __restrict__ in, int istride,
    const float* __restrict__ w, const float* __restrict__ bias,
    float* __restrict__ out, int ostride,
    int act, float inscale, bool accum, int tid)
{
    const int mb = (tid & 15) * 4;
    const int jb = (tid >> 4) * 4;
    const float* i0 = in + jb * istride;
    const float* i1 = i0 + istride;
    const float* i2 = i1 + istride;
    const float* i3 = i2 + istride;
    float r[4][4] = {};
    #pragma unroll 4
    for (int k = 0; k < 64; k += 4) {
        float4 w0 = *(const float4*)(w + (k + 0) * 64 + mb);
        float4 w1 = *(const float4*)(w + (k + 1) * 64 + mb);
        float4 w2 = *(const float4*)(w + (k + 2) * 64 + mb);
        float4 w3 = *(const float4*)(w + (k + 3) * 64 + mb);
        float4 a0 = *(const float4*)(i0 + k);
        float4 a1 = *(const float4*)(i1 + k);
        float4 a2 = *(const float4*)(i2 + k);
        float4 a3 = *(const float4*)(i3 + k);
        TILE4(r, a0.x, a1.x, a2.x, a3.x, w0)
        TILE4(r, a0.y, a1.y, a2.y, a3.y, w1)
        TILE4(r, a0.z, a1.z, a2.z, a3.z, w2)
        TILE4(r, a0.w, a1.w, a2.w, a3.w, w3)
    }
    #pragma unroll
    for (int u = 0; u < 4; u++) {
        float badd = bias ? bias[mb + u] : 0.f;
        #pragma unroll
        for (int v = 0; v < 4; v++) {
            float val = fmaf(r[v][u], inscale, badd);
            if (act == 1) val = gelu_exact(val);
            else if (act == 2) val = tanhf(val);
            float* o = out + (jb + v) * ostride + mb + u;
            if (accum) *o += val; else *o = val;
        }
    }
}

// 64x64x64 register-tile f32x2 GEMM: 64 threads, 8x8 per thread.
// A from global (row stride 64), W from smem. Result in o[8][8].
__device__ __forceinline__ void tile_mm8(
    const float* __restrict__ Ab, const float* __restrict__ Ws,
    int jb, int mb, const float* __restrict__ bs,
    const float* __restrict__ pre, int act, float o[8][8])
{
    unsigned long long A[8][4];
    #pragma unroll
    for (int r = 0; r < 8; r++)
        #pragma unroll
        for (int p = 0; p < 4; p++) A[r][p] = 0ull;
    const float* base = Ab + jb * 64;
    #pragma unroll 2
    for (int k = 0; k < 64; k += 4) {
        float4 av[8];
        #pragma unroll
        for (int r = 0; r < 8; r++) av[r] = *(const float4*)(base + r * 64 + k);
        #pragma unroll
        for (int kk = 0; kk < 4; kk++) {
            ulonglong2 wlo = *(const ulonglong2*)(Ws + (k + kk) * 64 + mb);
            ulonglong2 whi = *(const ulonglong2*)(Ws + (k + kk) * 64 + mb + 4);
            #pragma unroll
            for (int r = 0; r < 8; r++) {
                float a = (kk == 0) ? av[r].x : (kk == 1) ? av[r].y
                        : (kk == 2) ? av[r].z : av[r].w;
                unsigned long long ab = pk2(a, a);
                fma2(A[r][0], ab, wlo.x);
                fma2(A[r][1], ab, wlo.y);
                fma2(A[r][2], ab, whi.x);
                fma2(A[r][3], ab, whi.y);
            }
        }
    }
    float badd[8];
    #pragma unroll
    for (int u = 0; u < 8; u++)
        badd[u] = bs[mb + u] + (pre ? pre[mb + u] : 0.f);
    #pragma unroll
    for (int r = 0; r < 8; r++)
        #pragma unroll
        for (int p = 0; p < 4; p++) {
            float lo, hi;
            upk2(A[r][p], lo, hi);
            float v0 = lo + badd[2 * p];
            float v1 = hi + badd[2 * p + 1];
            if (act) { v0 = gelu_exact(v0); v1 = gelu_exact(v1); }
            o[r][2 * p] = v0; o[r][2 * p + 1] = v1;
        }
}

// ---- stage GEMM over all rows: Out = act(A @ W + bias [+ pre(b,i)]) ----
__global__ void __launch_bounds__(128, 3)
k_stage(const float* __restrict__ Aall, const float* __restrict__ Wg,
        const float* __restrict__ bias, int use_pre,
        float* __restrict__ Outall, int act)
{
    __shared__ float Ws[4096];
    __shared__ float bs[64];
    const int tid = threadIdx.x;
    for (int t = tid; t < 4096; t += 128) Ws[t] = Wg[t];
    if (tid < 64) bs[tid] = bias ? bias[tid] : 0.f;
    __syncthreads();
    const int q = blockIdx.x * 2 + (tid >> 6);   // (b,i) tile index
    const int t64 = tid & 63;
    const int mb = (t64 & 7) * 8, jb = (t64 >> 3) * 8;
    const float* Ab = Aall + (size_t)q * 4096;
    const float* pr = use_pre ? (g_pre + (size_t)q * 64) : (const float*)0;
    float o[8][8];
    tile_mm8(Ab, Ws, jb, mb, bs, pr, act, o);
    float* Ob = Outall + (size_t)q * 4096;
    #pragma unroll
    for (int r = 0; r < 8; r++) {
        *(float4*)(Ob + (jb + r) * 64 + mb)     = make_float4(o[r][0], o[r][1], o[r][2], o[r][3]);
        *(float4*)(Ob + (jb + r) * 64 + mb + 4) = make_float4(o[r][4], o[r][5], o[r][6], o[r][7]);
    }
}

// ---- S3: masked gelu GEMM + reduce over i into per-(b,half) partials ----
__global__ void __launch_bounds__(128, 3)
k_s3(const float* __restrict__ He, const float* __restrict__ Wg,
     const float* __restrict__ bias)
{
    extern __shared__ float s3m[];
    float* Ws  = s3m;            // 4096
    float* bs  = s3m + 4096;     // 64
    float* acc = s3m + 4160;     // 2 x 4096
    const int tid = threadIdx.x;
    for (int t = tid; t < 4096; t += 128) Ws[t] = Wg[t];
    if (tid < 64) bs[tid] = bias[tid];
    for (int t = tid; t < 8192; t += 128) acc[4160 - 4160 + t] = 0.f, ((void)0);
    for (int t = tid; t < 8192; t += 128) acc[t] = 0.f;
    __syncthreads();
    const int b = blockIdx.x >> 1, half = blockIdx.x & 1;
    const int unit = tid >> 6, t64 = tid & 63;
    const int mb = (t64 & 7) * 8, jb = (t64 >> 3) * 8;
    float* aU = acc + unit * 4096;
    for (int s = 0; s < 16; s++) {
        const int i = half * 32 + unit * 16 + s;
        const float* Ab = He + (size_t)(b * 64 + i) * 4096;
        float o[8][8];
        tile_mm8(Ab, Ws, jb, mb, bs, 0, 1, o);
        #pragma unroll
        for (int r = 0; r < 8; r++) {
            const int j = jb + r;
            if (j != i) {
                float4* a = (float4*)(aU + j * 64 + mb);
                float4 t0 = a[0], t1 = a[1];
                t0.x += o[r][0]; t0.y += o[r][1]; t0.z += o[r][2]; t0.w += o[r][3];
                t1.x += o[r][4]; t1.y += o[r][5]; t1.z += o[r][6]; t1.w += o[r][7];
                a[0] = t0; a[1] = t1;
            }
        }
    }
    __syncthreads();
    float* op = g_accp + (size_t)blockIdx.x * 4096;
    for (int t = tid; t < 4096; t += 128) op[t] = acc[t] + acc[4096 + t];
}

// ---- edge MLP hidden for all (b,i,j) rows ----
__global__ void __launch_bounds__(256)
k_edge(const float* __restrict__ x, const float* __restrict__ ew1,
       const float* __restrict__ eb1)
{
    __shared__ float W[256];
    __shared__ float bsh[64];
    const int tid = threadIdx.x;
    W[tid] = ew1[tid];
    if (tid < 64) bsh[tid] = eb1[tid];
    __syncthreads();
    const unsigned r = blockIdx.x * 256u + tid;
    const int b = r >> 12, ij = r & 4095, i = ij >> 6, j = ij & 63;
    float xi0 = x[b * 128 + i * 2], xi1 = x[b * 128 + i * 2 + 1];
    float xj0 = x[b * 128 + j * 2], xj1 = x[b * 128 + j * 2 + 1];
    float d0 = xj0 - xi0, d1 = xj1 - xi1;
    float r2 = d0 * d0 + d1 * d1;
    float rr = sqrtf(r2 + 1e-12f);
    float* o = g_tmp + (size_t)r * 64;
    #pragma unroll 4
    for (int m = 0; m < 64; m++) {
        float v = fmaf(d0, W[m], fmaf(d1, W[64 + m],
                  fmaf(rr, W[128 + m], fmaf(r2, W[192 + m], bsh[m]))));
        o[m] = gelu_exact(v);
    }
}

// ---- node MLP: hv + pre(l=0) per batch ----
__global__ void __launch_bounds__(256)
k_node(const float* __restrict__ x, const float* __restrict__ spin,
       const float* __restrict__ nw1, const float* __restrict__ nb1,
       const float* __restrict__ nw2, const float* __restrict__ nb2,
       const float* __restrict__ vw1, const float* __restrict__ vb1)
{
    extern __shared__ float nsm[];
    float* sW = nsm; float* sA = nsm + 4096; float* sB = nsm + 8192;
    float* sb = nsm + 12288; float* sxs = nsm + 12352; float* ssp = nsm + 12480;
    float* sw1 = nsm + 12544; float* sb1 = nsm + 12736;
    const int b = blockIdx.x, tid = threadIdx.x;
    if (tid < 128) sxs[tid] = x[b * 128 + tid];
    if (tid < 64)  ssp[tid] = spin[b * 64 + tid];
    if (tid < 192) sw1[tid] = nw1[tid];
    if (tid < 64)  sb1[tid] = nb1[tid];
    for (int t = tid; t < 4096; t += 256) sW[t] = nw2[t];
    if (tid < 64) sb[tid] = nb2[tid];
    __syncthreads();
    for (int t = tid; t < 4096; t += 256) {
        int i = t >> 6, h = t & 63;
        float v = fmaf(sxs[i * 2], sw1[h],
                  fmaf(sxs[i * 2 + 1], sw1[64 + h],
                  fmaf(ssp[i], sw1[128 + h], sb1[h])));
        sA[t] = gelu_exact(v);
    }
    __syncthreads();
    mm64(sA, 64, sW, sb, sB, 64, 0, 1.f, false, tid);   // hv
    __syncthreads();
    for (int t = tid; t < 4096; t += 256) { g_hv[b * 4096 + t] = sB[t]; sW[t] = vw1[t]; }
    if (tid < 64) sb[tid] = vb1[tid];
    __syncthreads();
    mm64(sB, 64, sW, sb, sA, 64, 0, 1.f, false, tid);   // pre(l=0)
    __syncthreads();
    for (int t = tid; t < 4096; t += 256) g_pre[b * 4096 + t] = sA[t];
}

// ---- aggregate partials, hv update, pre for next layer ----
__global__ void __launch_bounds__(256)
k_agg(const float* __restrict__ ew2, const float* __restrict__ eb2,
      const float* __restrict__ vw1, const float* __restrict__ vb1, int l)
{
    extern __shared__ float gsm[];
    float* sA = gsm; float* sW = gsm + 4096; float* sH = gsm + 8192; float* sb = gsm + 12288;
    const int b = blockIdx.x, tid = threadIdx.x;
    for (int t = tid; t < 4096; t += 256) {
        sA[t] = g_accp[(size_t)(b * 2) * 4096 + t] + g_accp[(size_t)(b * 2 + 1) * 4096 + t];
        sW[t] = ew2[t];
        sH[t] = g_hv[b * 4096 + t];
    }
    if (tid < 64) sb[tid] = eb2[tid];
    __syncthreads();
    mm64(sA, 64, sW, sb, sH, 64, 0, 1.0f / 63.0f, true, tid);
    __syncthreads();
    for (int t = tid; t < 4096; t += 256) g_hv[b * 4096 + t] = sH[t];
    if (l == 0) {
        for (int t = tid; t < 4096; t += 256) sW[t] = vw1[t];
        if (tid < 64) sb[tid] = vb1[tid];
        __syncthreads();
        mm64(sH, 64, sW, sb, sA, 64, 0, 1.f, false, tid);
        __syncthreads();
        for (int t = tid; t < 4096; t += 256) g_pre[b * 4096 + t] = sA[t];
    }
}

// ---- head ----
__global__ void __launch_bounds__(256)
k_head(const float* __restrict__ hw1, const float* __restrict__ hb1,
       const float* __restrict__ hw2, const float* __restrict__ hb2,
       const float* __restrict__ scale, float* __restrict__ out)
{
    extern __shared__ float hsm[];
    float* sH = hsm; float* sW = hsm + 4096; float* sT = hsm + 8192;
    float* sb = hsm + 12288; float* sdx = hsm + 12352; float* smn = hsm + 12480;
    const int b = blockIdx.x, tid = threadIdx.x;
    for (int t = tid; t < 4096; t += 256) { sH[t] = g_hv[b * 4096 + t]; sW[t] = hw1[t]; }
    if (tid < 64) sb[tid] = hb1[tid];
    __syncthreads();
    mm64(sH, 64, sW, sb, sT, 64, 2, 1.f, false, tid);
    __syncthreads();
    if (tid < 128) {
        int j = tid >> 1, d = tid & 1;
        float sp = log1pf(expf(scale[0]));
        float s = hb2[d];
        const float* a = sT + j * 64;
        #pragma unroll
        for (int k = 0; k < 64; k++) s = fmaf(a[k], hw2[k * 2 + d], s);
        sdx[tid] = s * sp;
    }
    __syncthreads();
    if (tid < 2) {
        float s = 0.f;
        #pragma unroll
        for (int j = 0; j < 64; j++) s += sdx[j * 2 + tid];
        smn[tid] = s * (1.0f / 64.0f);
    }
    __syncthreads();
    if (tid < 128) out[b * 128 + tid] = sdx[tid] - smn[tid & 1];
}

extern "C" void kernel_launch(void* const* d_in, const int* in_sizes, int n_in,
                              void* d_out, int out_size) {
    (void)out_size;
    const float* ptr[23];
    bool dict_order = (n_in >= 23 && in_sizes[0] == 16384 && in_sizes[2] == 192);
    if (dict_order) {
        for (int i = 0; i < 23; i++) ptr[i] = (const float*)d_in[i];
    } else {
        static const int alpha_to_dict[23] = {
            15, 17, 14, 16,  7,  9,  6,  8, 19, 21, 18, 20,
             3,  5,  2,  4, 22,  1, 11, 13, 10, 12,  0
        };
        for (int i = 0; i < 23; i++) ptr[alpha_to_dict[i]] = (const float*)d_in[i];
    }
    float* out = (float*)d_out;

    void *p_he_v, *p_tmp_v;
    cudaGetSymbolAddress(&p_he_v, g_he);
    cudaGetSymbolAddress(&p_tmp_v, g_tmp);
    float* p_he  = (float*)p_he_v;
    float* p_tmp = (float*)p_tmp_v;

    const size_t SZ_NODE = 12800u * 4u;
    const size_t SZ_S3   = 12352u * 4u;
    const size_t SZ_AGG  = 12352u * 4u;
    const size_t SZ_HEAD = 12482u * 4u;
    cudaFuncSetAttribute(k_node, cudaFuncAttributeMaxDynamicSharedMemorySize, (int)SZ_NODE);
    cudaFuncSetAttribute(k_s3,   cudaFuncAttributeMaxDynamicSharedMemorySize, (int)SZ_S3);
    cudaFuncSetAttribute(k_agg,  cudaFuncAttributeMaxDynamicSharedMemorySize, (int)SZ_AGG);
    cudaFuncSetAttribute(k_head, cudaFuncAttributeMaxDynamicSharedMemorySize, (int)SZ_HEAD);

    // node MLP -> hv, pre(l=0)
    k_node<<<128, 256, SZ_NODE>>>(ptr[0], ptr[1], ptr[2], ptr[3], ptr[4], ptr[5],
                                  ptr[10], ptr[11]);
    // edge MLP hidden -> g_tmp
    k_edge<<<2048, 256>>>(ptr[0], ptr[6], ptr[7]);
    // he0 = hidden @ edge_w2 + b2 -> g_he
    k_stage<<<4096, 128>>>(p_tmp, ptr[8], ptr[9], 0, p_he, 0);

    for (int l = 0; l < 2; l++) {
        // S1: gelu(he @ Wv1he + pre) -> g_tmp
        k_stage<<<4096, 128>>>(p_he, ptr[10] + l * 8192 + 4096, (const float*)0, 1, p_tmp, 1);
        // S2: he' = hidden @ Wv2 + b2 -> g_he
        k_stage<<<4096, 128>>>(p_tmp, ptr[12] + l * 4096, ptr[13] + l * 64, 0, p_he, 0);
        // S3: masked gelu(he' @ We1 + b1) reduced over i -> g_accp
        k_s3<<<256, 128, SZ_S3>>>(p_he, ptr[14] + l * 4096, ptr[15] + l * 64);
        // aggregate + hv update (+ pre for l=1)
        k_agg<<<128, 256, SZ_AGG>>>(ptr[16] + l * 4096, ptr[17] + l * 64,
                                    ptr[10] + 8192, ptr[11] + 64, l);
    }
    // head
    k_head<<<128, 256, SZ_HEAD>>>(ptr[18], ptr[19], ptr[20], ptr[21], ptr[22], out);
}

// round 10
// speedup vs baseline: 1.0773x; 1.0773x over previous
#include <cuda_runtime.h>
#include <math.h>
#include <stdint.h>

// BackflowNet: B=128, N=64, D=2, H=64, M=64, L=2.
// R10: fused per-(batch,half) i-loop kernel at 2 CTAs/SM (256 CTAs, ~110KB smem),
// f32x2 FFMA2 8x8 register tiles, GEMM3 accumulates in registers (no smem acc).
// Per-batch small stages (node/agg/head) as separate kernels (from R9, verified).

__device__ float g_he [128u*64u*64u*64u];   // [b][i][j][m]
__device__ float g_hv [128u*64u*64u];       // [b][j][h]
__device__ float g_pre[128u*64u*64u];       // [b][i][m]
__device__ float g_accp[256u*64u*64u];      // [(b,half)][j][m]

__device__ __forceinline__ float gelu_exact(float x) {
    return 0.5f * x * (1.0f + erff(x * 0.70710678118654752f));
}
__device__ __forceinline__ unsigned long long pk2(float lo, float hi) {
    unsigned long long r;
    asm("mov.b64 %0, {%1, %2};" : "=l"(r) : "f"(lo), "f"(hi));
    return r;
}
__device__ __forceinline__ void upk2(unsigned long long v, float& lo, float& hi) {
    asm("mov.b64 {%0, %1}, %2;" : "=f"(lo), "=f"(hi) : "l"(v));
}
__device__ __forceinline__ void fma2(unsigned long long& d, unsigned long long a, unsigned long long b) {
    asm("fma.rn.f32x2 %0, %1, %2, %0;" : "+l"(d) : "l"(a), "l"(b));
}

#define RANK1(rr, av, wv) \
    rr[0]=fmaf(av, wv.x, rr[0]); rr[1]=fmaf(av, wv.y, rr[1]); \
    rr[2]=fmaf(av, wv.z, rr[2]); rr[3]=fmaf(av, wv.w, rr[3]);
#define TILE4(R, a0v, a1v, a2v, a3v, W) \
    RANK1(R[0], a0v, W) RANK1(R[1], a1v, W) RANK1(R[2], a2v, W) RANK1(R[3], a3v, W)

// scalar 64x64x64 GEMM for per-batch small stages (256 threads)
__device__ __forceinline__ void mm64(
    const float* __restrict__ in, int istride,
    const float* __restrict__ w, const float* __restrict__ bias,
    float* __restrict__ out, int ostride,
    int act, float inscale, bool accum, int tid)
{
    const int mb = (tid & 15) * 4;
    const int jb = (tid >> 4) * 4;
    const float* i0 = in + jb * istride;
    const float* i1 = i0 + istride;
    const float* i2 = i1 + istride;
    const float* i3 = i2 + istride;
    float r[4][4] = {};
    #pragma unroll 4
    for (int k = 0; k < 64; k += 4) {
        float4 w0 = *(const float4*)(w + (k + 0) * 64 + mb);
        float4 w1 = *(const float4*)(w + (k + 1) * 64 + mb);
        float4 w2 = *(const float4*)(w + (k + 2) * 64 + mb);
        float4 w3 = *(const float4*)(w + (k + 3) * 64 + mb);
        float4 a0 = *(const float4*)(i0 + k);
        float4 a1 = *(const float4*)(i1 + k);
        float4 a2 = *(const float4*)(i2 + k);
        float4 a3 = *(const float4*)(i3 + k);
        TILE4(r, a0.x, a1.x, a2.x, a3.x, w0)
        TILE4(r, a0.y, a1.y, a2.y, a3.y, w1)
        TILE4(r, a0.z, a1.z, a2.z, a3.z, w2)
        TILE4(r, a0.w, a1.w, a2.w, a3.w, w3)
    }
    #pragma unroll
    for (int u = 0; u < 4; u++) {
        float badd = bias ? bias[mb + u] : 0.f;
        #pragma unroll
        for (int v = 0; v < 4; v++) {
            float val = fmaf(r[v][u], inscale, badd);
            if (act == 1) val = gelu_exact(val);
            else if (act == 2) val = tanhf(val);
            float* o = out + (jb + v) * ostride + mb + u;
            if (accum) *o += val; else *o = val;
        }
    }
}

// 64x64x64 f32x2 GEMM tile: 64 threads, 8x8 per thread. A via pointer+stride,
// W from smem, epilogue badd[8] + optional act into o[8][8]. No barriers.
__device__ __forceinline__ void tile_mm8s(
    const float* __restrict__ Ab, int astr, const float* __restrict__ Ws,
    int jb, int mb, const float* __restrict__ badd, int act, float o[8][8])
{
    unsigned long long A[8][4];
    #pragma unroll
    for (int r = 0; r < 8; r++)
        #pragma unroll
        for (int p = 0; p < 4; p++) A[r][p] = 0ull;
    const float* base = Ab + jb * astr;
    #pragma unroll 2
    for (int k = 0; k < 64; k += 4) {
        float4 av[8];
        #pragma unroll
        for (int r = 0; r < 8; r++) av[r] = *(const float4*)(base + r * astr + k);
        #pragma unroll
        for (int kk = 0; kk < 4; kk++) {
            ulonglong2 wlo = *(const ulonglong2*)(Ws + (k + kk) * 64 + mb);
            ulonglong2 whi = *(const ulonglong2*)(Ws + (k + kk) * 64 + mb + 4);
            #pragma unroll
            for (int r = 0; r < 8; r++) {
                float a = (kk == 0) ? av[r].x : (kk == 1) ? av[r].y
                        : (kk == 2) ? av[r].z : av[r].w;
                unsigned long long ab = pk2(a, a);
                fma2(A[r][0], ab, wlo.x);
                fma2(A[r][1], ab, wlo.y);
                fma2(A[r][2], ab, whi.x);
                fma2(A[r][3], ab, whi.y);
            }
        }
    }
    #pragma unroll
    for (int r = 0; r < 8; r++)
        #pragma unroll
        for (int p = 0; p < 4; p++) {
            float lo, hi;
            upk2(A[r][p], lo, hi);
            float v0 = lo + badd[2 * p];
            float v1 = hi + badd[2 * p + 1];
            if (act) { v0 = gelu_exact(v0); v1 = gelu_exact(v1); }
            o[r][2 * p] = v0; o[r][2 * p + 1] = v1;
        }
}

// SMEM layout for k_iloop (floats)
#define IL_T0    0          // 2 tiles [64][68]
#define IL_W0    8704       // edge_w2 (l=0 only)
#define IL_W1    12800      // v2e_w1 he-half
#define IL_W2    16896      // v2e_w2
#define IL_W3    20992      // e2v_w1
#define IL_PRE   25088      // [32][64]
#define IL_XS    27136      // [128]
#define IL_EW1   27264      // [4][64]
#define IL_F4    27520      // [2][64][4]
#define IL_BE2   28032
#define IL_BV2   28096
#define IL_BEV1  28160
#define IL_BEB1  28224
#define IL_FLOATS 28288
#define IL_BYTES (IL_FLOATS * 4)

__global__ void __launch_bounds__(128, 2)
k_iloop(int l, const float* __restrict__ x,
        const float* __restrict__ ew1, const float* __restrict__ eb1,
        const float* __restrict__ ew2, const float* __restrict__ eb2,
        const float* __restrict__ vw1he, const float* __restrict__ vb2,
        const float* __restrict__ vw2,
        const float* __restrict__ cw1, const float* __restrict__ cb1)
{
    extern __shared__ float smil[];
    const int tid = threadIdx.x;
    const int unit = tid >> 6, t64 = tid & 63;
    const int mb = (t64 & 7) * 8, jb = (t64 >> 3) * 8;
    const int b = blockIdx.x >> 1, half = blockIdx.x & 1;
    float* T    = smil + IL_T0 + unit * 4352;
    float* W0   = smil + IL_W0;
    float* W1   = smil + IL_W1;
    float* W2   = smil + IL_W2;
    float* W3   = smil + IL_W3;
    float* PRE  = smil + IL_PRE;
    float* XS   = smil + IL_XS;
    float* EW1  = smil + IL_EW1;
    float* F4u  = smil + IL_F4 + unit * 256;
    float* BE2  = smil + IL_BE2;
    float* BV2  = smil + IL_BV2;
    float* BEV1 = smil + IL_BEV1;
    float* BEB1 = smil + IL_BEB1;

    // stage weights + pre
    for (int t = tid; t < 4096; t += 128) {
        W1[t] = vw1he[t]; W2[t] = vw2[t]; W3[t] = cw1[t];
    }
    if (l == 0) {
        for (int t = tid; t < 4096; t += 128) W0[t] = ew2[t];
        if (tid < 64) { EW1[tid] = ew1[tid]; EW1[64+tid] = ew1[64+tid];
                        EW1[128+tid] = ew1[128+tid]; EW1[192+tid] = ew1[192+tid];
                        BE2[tid] = eb2[tid]; BEB1[tid] = eb1[tid]; }
        XS[tid] = x[b * 128 + tid];
    }
    if (tid < 64) { BV2[tid] = vb2[tid]; BEV1[tid] = cb1[tid]; }
    for (int t = tid; t < 2048; t += 128)
        PRE[t] = g_pre[b * 4096 + half * 2048 + t];
    __syncthreads();

    float accR[8][8] = {};
    float badd[8], o[8][8];

    for (int iq = 0; iq < 16; iq++) {
        const int il = iq * 2 + unit;
        const int i = half * 32 + il;
        if (l == 0) {
            {   // geometry features for this unit's source row
                int j = t64;
                float d0 = XS[j * 2]     - XS[i * 2];
                float d1 = XS[j * 2 + 1] - XS[i * 2 + 1];
                float r2 = d0 * d0 + d1 * d1;
                float rr = sqrtf(r2 + 1e-12f);
                float* f = F4u + j * 4;
                f[0] = d0; f[1] = d1; f[2] = rr; f[3] = r2;
            }
            __syncthreads();
            {   // edge MLP hidden: thread owns column m
                int m = t64;
                float w0 = EW1[m], w1 = EW1[64 + m], w2 = EW1[128 + m], w3 = EW1[192 + m];
                float bb = BEB1[m];
                #pragma unroll 4
                for (int j = 0; j < 64; j++) {
                    const float* f = F4u + j * 4;
                    float v = fmaf(f[0], w0, fmaf(f[1], w1, fmaf(f[2], w2, fmaf(f[3], w3, bb))));
                    T[j * 68 + m] = gelu_exact(v);
                }
            }
            __syncthreads();
            // he0 = hidden @ edge_w2 + b2
            #pragma unroll
            for (int u = 0; u < 8; u++) badd[u] = BE2[mb + u];
            tile_mm8s(T, 68, W0, jb, mb, badd, 0, o);
            __syncthreads();
            #pragma unroll
            for (int r = 0; r < 8; r++) {
                *(float4*)(T + (jb + r) * 68 + mb)     = make_float4(o[r][0], o[r][1], o[r][2], o[r][3]);
                *(float4*)(T + (jb + r) * 68 + mb + 4) = make_float4(o[r][4], o[r][5], o[r][6], o[r][7]);
            }
            __syncthreads();
            // hidden = gelu(he0 @ W1 + pre[i])
            #pragma unroll
            for (int u = 0; u < 8; u++) badd[u] = PRE[il * 64 + mb + u];
            tile_mm8s(T, 68, W1, jb, mb, badd, 1, o);
            __syncthreads();
        } else {
            // hidden = gelu(he @ W1 + pre[i]) with A from global he
            const float* Ab = g_he + (size_t)(b * 64 + i) * 4096;
            #pragma unroll
            for (int u = 0; u < 8; u++) badd[u] = PRE[il * 64 + mb + u];
            tile_mm8s(Ab, 64, W1, jb, mb, badd, 1, o);
            __syncthreads();
        }
        #pragma unroll
        for (int r = 0; r < 8; r++) {
            *(float4*)(T + (jb + r) * 68 + mb)     = make_float4(o[r][0], o[r][1], o[r][2], o[r][3]);
            *(float4*)(T + (jb + r) * 68 + mb + 4) = make_float4(o[r][4], o[r][5], o[r][6], o[r][7]);
        }
        __syncthreads();
        // he' = hidden @ W2 + vb2  (mirror to g_he in layer 0)
        #pragma unroll
        for (int u = 0; u < 8; u++) badd[u] = BV2[mb + u];
        tile_mm8s(T, 68, W2, jb, mb, badd, 0, o);
        __syncthreads();
        {
            float* gm = g_he + (size_t)(b * 64 + i) * 4096;
            #pragma unroll
            for (int r = 0; r < 8; r++) {
                float4 lo4 = make_float4(o[r][0], o[r][1], o[r][2], o[r][3]);
                float4 hi4 = make_float4(o[r][4], o[r][5], o[r][6], o[r][7]);
                *(float4*)(T + (jb + r) * 68 + mb)     = lo4;
                *(float4*)(T + (jb + r) * 68 + mb + 4) = hi4;
                if (l == 0) {
                    *(float4*)(gm + (jb + r) * 64 + mb)     = lo4;
                    *(float4*)(gm + (jb + r) * 64 + mb + 4) = hi4;
                }
            }
        }
        __syncthreads();
        // gv = gelu(he' @ W3 + cb1), masked accumulate into registers
        #pragma unroll
        for (int u = 0; u < 8; u++) badd[u] = BEV1[mb + u];
        tile_mm8s(T, 68, W3, jb, mb, badd, 1, o);
        #pragma unroll
        for (int r = 0; r < 8; r++) {
            if (jb + r != i) {
                #pragma unroll
                for (int u = 0; u < 8; u++) accR[r][u] += o[r][u];
            }
        }
        __syncthreads();   // GEMM3 reads done before next iq rewrites T
    }

    // combine the two units' register accumulators -> g_accp[(b,half)]
    if (unit == 0) {
        float* T0 = smil + IL_T0;
        #pragma unroll
        for (int r = 0; r < 8; r++) {
            *(float4*)(T0 + (jb + r) * 68 + mb)     = make_float4(accR[r][0], accR[r][1], accR[r][2], accR[r][3]);
            *(float4*)(T0 + (jb + r) * 68 + mb + 4) = make_float4(accR[r][4], accR[r][5], accR[r][6], accR[r][7]);
        }
    }
    __syncthreads();
    if (unit == 1) {
        const float* T0 = smil + IL_T0;
        float* op = g_accp + (size_t)blockIdx.x * 4096;
        #pragma unroll
        for (int r = 0; r < 8; r++) {
            float4 p0 = *(const float4*)(T0 + (jb + r) * 68 + mb);
            float4 p1 = *(const float4*)(T0 + (jb + r) * 68 + mb + 4);
            *(float4*)(op + (jb + r) * 64 + mb) =
                make_float4(p0.x + accR[r][0], p0.y + accR[r][1], p0.z + accR[r][2], p0.w + accR[r][3]);
            *(float4*)(op + (jb + r) * 64 + mb + 4) =
                make_float4(p1.x + accR[r][4], p1.y + accR[r][5], p1.z + accR[r][6], p1.w + accR[r][7]);
        }
    }
}

// ---- node MLP: hv + pre(l=0) per batch ----
__global__ void __launch_bounds__(256)
k_node(const float* __restrict__ x, const float* __restrict__ spin,
       const float* __restrict__ nw1, const float* __restrict__ nb1,
       const float* __restrict__ nw2, const float* __restrict__ nb2,
       const float* __restrict__ vw1, const float* __restrict__ vb1)
{
    extern __shared__ float nsm[];
    float* sW = nsm; float* sA = nsm + 4096; float* sB = nsm + 8192;
    float* sb = nsm + 12288; float* sxs = nsm + 12352; float* ssp = nsm + 12480;
    float* sw1 = nsm + 12544; float* sb1 = nsm + 12736;
    const int b = blockIdx.x, tid = threadIdx.x;
    if (tid < 128) sxs[tid] = x[b * 128 + tid];
    if (tid < 64)  ssp[tid] = spin[b * 64 + tid];
    if (tid < 192) sw1[tid] = nw1[tid];
    if (tid < 64)  sb1[tid] = nb1[tid];
    for (int t = tid; t < 4096; t += 256) sW[t] = nw2[t];
    if (tid < 64) sb[tid] = nb2[tid];
    __syncthreads();
    for (int t = tid; t < 4096; t += 256) {
        int i = t >> 6, h = t & 63;
        float v = fmaf(sxs[i * 2], sw1[h],
                  fmaf(sxs[i * 2 + 1], sw1[64 + h],
                  fmaf(ssp[i], sw1[128 + h], sb1[h])));
        sA[t] = gelu_exact(v);
    }
    __syncthreads();
    mm64(sA, 64, sW, sb, sB, 64, 0, 1.f, false, tid);   // hv
    __syncthreads();
    for (int t = tid; t < 4096; t += 256) { g_hv[b * 4096 + t] = sB[t]; sW[t] = vw1[t]; }
    if (tid < 64) sb[tid] = vb1[tid];
    __syncthreads();
    mm64(sB, 64, sW, sb, sA, 64, 0, 1.f, false, tid);   // pre(l=0)
    __syncthreads();
    for (int t = tid; t < 4096; t += 256) g_pre[b * 4096 + t] = sA[t];
}

// ---- aggregate partials, hv update, pre for next layer ----
__global__ void __launch_bounds__(256)
k_agg(const float* __restrict__ ew2, const float* __restrict__ eb2,
      const float* __restrict__ vw1, const float* __restrict__ vb1, int l)
{
    extern __shared__ float gsm[];
    float* sA = gsm; float* sW = gsm + 4096; float* sH = gsm + 8192; float* sb = gsm + 12288;
    const int b = blockIdx.x, tid = threadIdx.x;
    for (int t = tid; t < 4096; t += 256) {
        sA[t] = g_accp[(size_t)(b * 2) * 4096 + t] + g_accp[(size_t)(b * 2 + 1) * 4096 + t];
        sW[t] = ew2[t];
        sH[t] = g_hv[b * 4096 + t];
    }
    if (tid < 64) sb[tid] = eb2[tid];
    __syncthreads();
    mm64(sA, 64, sW, sb, sH, 64, 0, 1.0f / 63.0f, true, tid);
    __syncthreads();
    for (int t = tid; t < 4096; t += 256) g_hv[b * 4096 + t] = sH[t];
    if (l == 0) {
        for (int t = tid; t < 4096; t += 256) sW[t] = vw1[t];
        if (tid < 64) sb[tid] = vb1[tid];
        __syncthreads();
        mm64(sH, 64, sW, sb, sA, 64, 0, 1.f, false, tid);
        __syncthreads();
        for (int t = tid; t < 4096; t += 256) g_pre[b * 4096 + t] = sA[t];
    }
}

// ---- head ----
__global__ void __launch_bounds__(256)
k_head(const float* __restrict__ hw1, const float* __restrict__ hb1,
       const float* __restrict__ hw2, const float* __restrict__ hb2,
       const float* __restrict__ scale, float* __restrict__ out)
{
    extern __shared__ float hsm[];
    float* sH = hsm; float* sW = hsm + 4096; float* sT = hsm + 8192;
    float* sb = hsm + 12288; float* sdx = hsm + 12352; float* smn = hsm + 12480;
    const int b = blockIdx.x, tid = threadIdx.x;
    for (int t = tid; t < 4096; t += 256) { sH[t] = g_hv[b * 4096 + t]; sW[t] = hw1[t]; }
    if (tid < 64) sb[tid] = hb1[tid];
    __syncthreads();
    mm64(sH, 64, sW, sb, sT, 64, 2, 1.f, false, tid);
    __syncthreads();
    if (tid < 128) {
        int j = tid >> 1, d = tid & 1;
        float sp = log1pf(expf(scale[0]));
        float s = hb2[d];
        const float* a = sT + j * 64;
        #pragma unroll
        for (int k = 0; k < 64; k++) s = fmaf(a[k], hw2[k * 2 + d], s);
        sdx[tid] = s * sp;
    }
    __syncthreads();
    if (tid < 2) {
        float s = 0.f;
        #pragma unroll
        for (int j = 0; j < 64; j++) s += sdx[j * 2 + tid];
        smn[tid] = s * (1.0f / 64.0f);
    }
    __syncthreads();
    if (tid < 128) out[b * 128 + tid] = sdx[tid] - smn[tid & 1];
}

extern "C" void kernel_launch(void* const* d_in, const int* in_sizes, int n_in,
                              void* d_out, int out_size) {
    (void)out_size;
    const float* ptr[23];
    bool dict_order = (n_in >= 23 && in_sizes[0] == 16384 && in_sizes[2] == 192);
    if (dict_order) {
        for (int i = 0; i < 23; i++) ptr[i] = (const float*)d_in[i];
    } else {
        static const int alpha_to_dict[23] = {
            15, 17, 14, 16,  7,  9,  6,  8, 19, 21, 18, 20,
             3,  5,  2,  4, 22,  1, 11, 13, 10, 12,  0
        };
        for (int i = 0; i < 23; i++) ptr[alpha_to_dict[i]] = (const float*)d_in[i];
    }
    float* out = (float*)d_out;

    const size_t SZ_NODE = 12800u * 4u;
    const size_t SZ_AGG  = 12352u * 4u;
    const size_t SZ_HEAD = 12482u * 4u;
    cudaFuncSetAttribute(k_iloop, cudaFuncAttributeMaxDynamicSharedMemorySize, IL_BYTES);
    cudaFuncSetAttribute(k_node, cudaFuncAttributeMaxDynamicSharedMemorySize, (int)SZ_NODE);
    cudaFuncSetAttribute(k_agg,  cudaFuncAttributeMaxDynamicSharedMemorySize, (int)SZ_AGG);
    cudaFuncSetAttribute(k_head, cudaFuncAttributeMaxDynamicSharedMemorySize, (int)SZ_HEAD);

    // node MLP -> hv, pre(l=0)
    k_node<<<128, 256, SZ_NODE>>>(ptr[0], ptr[1], ptr[2], ptr[3], ptr[4], ptr[5],
                                  ptr[10], ptr[11]);
    for (int l = 0; l < 2; l++) {
        k_iloop<<<256, 128, IL_BYTES>>>(l, ptr[0],
            ptr[6], ptr[7], ptr[8], ptr[9],
            ptr[10] + l * 8192 + 4096, ptr[13] + l * 64, ptr[12] + l * 4096,
            ptr[14] + l * 4096, ptr[15] + l * 64);
        k_agg<<<128, 256, SZ_AGG>>>(ptr[16] + l * 4096, ptr[17] + l * 64,
                                    ptr[10] + 8192, ptr[11] + 64, l);
    }
    k_head<<<128, 256, SZ_HEAD>>>(ptr[18], ptr[19], ptr[20], ptr[21], ptr[22], out);
}

// round 11
// speedup vs baseline: 1.5690x; 1.4564x over previous
#include <cuda_runtime.h>
#include <math.h>
#include <stdint.h>

// BackflowNet: B=128, N=64, D=2, H=64, M=64, L=2.
// R11: algebraic fusion — all linear edge-stages collapsed via precomputed
// weight products (W_A..W_D). 4 GEMMs/edge instead of 7, no he materialization.
//   pass A: edgeMLP -> hidden0 = gelu(. @ W_A + pre0) [stored] -> gv0 (acc)
//   k_agg(l=0) -> hv1, pre1
//   pass B: hidden1 = gelu(hidden0 @ W_C + pre1) -> gv1 (acc)
//   k_agg(l=1) -> hv2 -> head
// f32x2 FFMA2 8x8 register tiles; 2-unit 128-thread CTAs; acc in registers.

__device__ float g_hid0[128u*64u*64u*64u];  // [b][i][j][m] hidden0 (post-gelu)
__device__ float g_hv [128u*64u*64u];
__device__ float g_pre[128u*64u*64u];
__device__ float g_accp[256u*64u*64u];
__device__ float g_Wf[4*4096];              // W_A, W_B, W_C, W_D
__device__ float g_bf[4*64];                // fused bias rows

__device__ __forceinline__ float gelu_exact(float x) {
    return 0.5f * x * (1.0f + erff(x * 0.70710678118654752f));
}
__device__ __forceinline__ unsigned long long pk2(float lo, float hi) {
    unsigned long long r;
    asm("mov.b64 %0, {%1, %2};" : "=l"(r) : "f"(lo), "f"(hi));
    return r;
}
__device__ __forceinline__ void upk2(unsigned long long v, float& lo, float& hi) {
    asm("mov.b64 {%0, %1}, %2;" : "=f"(lo), "=f"(hi) : "l"(v));
}
__device__ __forceinline__ void fma2(unsigned long long& d, unsigned long long a, unsigned long long b) {
    asm("fma.rn.f32x2 %0, %1, %2, %0;" : "+l"(d) : "l"(a), "l"(b));
}

#define RANK1(rr, av, wv) \
    rr[0]=fmaf(av, wv.x, rr[0]); rr[1]=fmaf(av, wv.y, rr[1]); \
    rr[2]=fmaf(av, wv.z, rr[2]); rr[3]=fmaf(av, wv.w, rr[3]);
#define TILE4(R, a0v, a1v, a2v, a3v, W) \
    RANK1(R[0], a0v, W) RANK1(R[1], a1v, W) RANK1(R[2], a2v, W) RANK1(R[3], a3v, W)

// scalar 64x64x64 GEMM for per-batch small stages (256 threads)
__device__ __forceinline__ void mm64(
    const float* __restrict__ in, int istride,
    const float* __restrict__ w, const float* __restrict__ bias,
    float* __restrict__ out, int ostride,
    int act, float inscale, bool accum, int tid)
{
    const int mb = (tid & 15) * 4;
    const int jb = (tid >> 4) * 4;
    const float* i0 = in + jb * istride;
    const float* i1 = i0 + istride;
    const float* i2 = i1 + istride;
    const float* i3 = i2 + istride;
    float r[4][4] = {};
    #pragma unroll 4
    for (int k = 0; k < 64; k += 4) {
        float4 w0 = *(const float4*)(w + (k + 0) * 64 + mb);
        float4 w1 = *(const float4*)(w + (k + 1) * 64 + mb);
        float4 w2 = *(const float4*)(w + (k + 2) * 64 + mb);
        float4 w3 = *(const float4*)(w + (k + 3) * 64 + mb);
        float4 a0 = *(const float4*)(i0 + k);
        float4 a1 = *(const float4*)(i1 + k);
        float4 a2 = *(const float4*)(i2 + k);
        float4 a3 = *(const float4*)(i3 + k);
        TILE4(r, a0.x, a1.x, a2.x, a3.x, w0)
        TILE4(r, a0.y, a1.y, a2.y, a3.y, w1)
        TILE4(r, a0.z, a1.z, a2.z, a3.z, w2)
        TILE4(r, a0.w, a1.w, a2.w, a3.w, w3)
    }
    #pragma unroll
    for (int u = 0; u < 4; u++) {
        float badd = bias ? bias[mb + u] : 0.f;
        #pragma unroll
        for (int v = 0; v < 4; v++) {
            float val = fmaf(r[v][u], inscale, badd);
            if (act == 1) val = gelu_exact(val);
            else if (act == 2) val = tanhf(val);
            float* o = out + (jb + v) * ostride + mb + u;
            if (accum) *o += val; else *o = val;
        }
    }
}

// 64x64x64 f32x2 GEMM tile, 64 threads, 8x8/thread, act = gelu always.
// MODE 0: __syncthreads; write outT (stride 68) [+ optional gout stride 64]; __syncthreads.
// MODE 1: masked accumulate into accR (row jb+r != maski).
template<int MODE>
__device__ __forceinline__ void tile_gemm(
    const float* Ab, int astr, const float* __restrict__ Ws,
    int jb, int mb, const float badd[8],
    float* outT, float* gout, float (*accR)[8], int maski)
{
    unsigned long long A[8][4];
    #pragma unroll
    for (int r = 0; r < 8; r++)
        #pragma unroll
        for (int p = 0; p < 4; p++) A[r][p] = 0ull;
    const float* base = Ab + jb * astr;
    #pragma unroll 2
    for (int k = 0; k < 64; k += 4) {
        float4 av[8];
        #pragma unroll
        for (int r = 0; r < 8; r++) av[r] = *(const float4*)(base + r * astr + k);
        #pragma unroll
        for (int kk = 0; kk < 4; kk++) {
            ulonglong2 wlo = *(const ulonglong2*)(Ws + (k + kk) * 64 + mb);
            ulonglong2 whi = *(const ulonglong2*)(Ws + (k + kk) * 64 + mb + 4);
            #pragma unroll
            for (int r = 0; r < 8; r++) {
                float a = (kk == 0) ? av[r].x : (kk == 1) ? av[r].y
                        : (kk == 2) ? av[r].z : av[r].w;
                unsigned long long ab = pk2(a, a);
                fma2(A[r][0], ab, wlo.x);
                fma2(A[r][1], ab, wlo.y);
                fma2(A[r][2], ab, whi.x);
                fma2(A[r][3], ab, whi.y);
            }
        }
    }
    if (MODE == 0) {
        __syncthreads();   // T readers (prev stage) done before in-place writes
        #pragma unroll
        for (int r = 0; r < 8; r++) {
            float o[8];
            #pragma unroll
            for (int p = 0; p < 4; p++) {
                float lo, hi;
                upk2(A[r][p], lo, hi);
                o[2 * p]     = gelu_exact(lo + badd[2 * p]);
                o[2 * p + 1] = gelu_exact(hi + badd[2 * p + 1]);
            }
            float4 lo4 = make_float4(o[0], o[1], o[2], o[3]);
            float4 hi4 = make_float4(o[4], o[5], o[6], o[7]);
            *(float4*)(outT + (jb + r) * 68 + mb)     = lo4;
            *(float4*)(outT + (jb + r) * 68 + mb + 4) = hi4;
            if (gout) {
                *(float4*)(gout + (jb + r) * 64 + mb)     = lo4;
                *(float4*)(gout + (jb + r) * 64 + mb + 4) = hi4;
            }
        }
        __syncthreads();   // writes visible before next stage reads
    } else {
        #pragma unroll
        for (int r = 0; r < 8; r++) {
            if (jb + r != maski) {
                #pragma unroll
                for (int p = 0; p < 4; p++) {
                    float lo, hi;
                    upk2(A[r][p], lo, hi);
                    accR[r][2 * p]     += gelu_exact(lo + badd[2 * p]);
                    accR[r][2 * p + 1] += gelu_exact(hi + badd[2 * p + 1]);
                }
            }
        }
    }
}

// ---- fused weight precompute: g_Wf[s] = L @ R, g_bf[s] = bL @ R (+ extra) ----
__global__ void __launch_bounds__(256)
k_wfuse(const float* __restrict__ ew2, const float* __restrict__ eb2,
        const float* __restrict__ vw1, const float* __restrict__ vw2,
        const float* __restrict__ vb2,
        const float* __restrict__ cw1, const float* __restrict__ cb1)
{
    __shared__ float sL[4096], sR[4096];
    const int s = blockIdx.x, tid = threadIdx.x;
    const float *L, *R, *bL, *extra = 0;
    if (s == 0)      { L = ew2;        R = vw1 + 4096;         bL = eb2; }
    else if (s == 1) { L = vw2;        R = cw1;                bL = vb2; extra = cb1; }
    else if (s == 2) { L = vw2;        R = vw1 + 8192 + 4096;  bL = vb2; }
    else             { L = vw2 + 4096; R = cw1 + 4096;         bL = vb2 + 64; extra = cb1 + 64; }
    for (int t = tid; t < 4096; t += 256) { sL[t] = L[t]; sR[t] = R[t]; }
    __syncthreads();
    mm64(sL, 64, sR, 0, g_Wf + s * 4096, 64, 0, 1.f, false, tid);
    if (tid < 64) {
        float acc = extra ? extra[tid] : 0.f;
        #pragma unroll 4
        for (int k = 0; k < 64; k++) acc = fmaf(bL[k], sR[k * 64 + tid], acc);
        g_bf[s * 64 + tid] = acc;
    }
}

// ---- pass A: edgeMLP -> hidden0 (store) -> gv0 (masked acc) ----
#define PA_T0   0        // 2 x [64][68]
#define PA_WA   8704
#define PA_WB   12800
#define PA_PRE  16896    // [32][64]
#define PA_F4   18944    // [2][64][4]
#define PA_XS   19456
#define PA_EW1  19584    // [4][64]
#define PA_BEB1 19840
#define PA_BFA  19904
#define PA_BB   19968
#define PA_FLOATS 20032
#define PA_BYTES (PA_FLOATS * 4)

__global__ void __launch_bounds__(128, 2)
k_passA(const float* __restrict__ x, const float* __restrict__ ew1,
        const float* __restrict__ eb1)
{
    extern __shared__ float sa[];
    const int tid = threadIdx.x;
    const int unit = tid >> 6, t64 = tid & 63;
    const int mb = (t64 & 7) * 8, jb = (t64 >> 3) * 8;
    const int b = blockIdx.x >> 1, half = blockIdx.x & 1;
    float* T   = sa + PA_T0 + unit * 4352;
    float* WA  = sa + PA_WA;
    float* WB  = sa + PA_WB;
    float* PRE = sa + PA_PRE;
    float* F4u = sa + PA_F4 + unit * 256;
    float* XS  = sa + PA_XS;
    float* EW1 = sa + PA_EW1;
    float* BEB1 = sa + PA_BEB1;
    float* BFA = sa + PA_BFA;
    float* BB  = sa + PA_BB;

    for (int t = tid; t < 4096; t += 128) { WA[t] = g_Wf[t]; WB[t] = g_Wf[4096 + t]; }
    for (int t = tid; t < 2048; t += 128) PRE[t] = g_pre[b * 4096 + half * 2048 + t];
    if (tid < 128) XS[tid] = x[b * 128 + tid];
    if (tid < 64) {
        EW1[tid] = ew1[tid]; EW1[64 + tid] = ew1[64 + tid];
        EW1[128 + tid] = ew1[128 + tid]; EW1[192 + tid] = ew1[192 + tid];
        BEB1[tid] = eb1[tid]; BFA[tid] = g_bf[tid]; BB[tid] = g_bf[64 + tid];
    }
    __syncthreads();

    float accR[8][8] = {};
    float badd[8];
    for (int iq = 0; iq < 16; iq++) {
        const int il = iq * 2 + unit;
        const int i = half * 32 + il;
        {   // geometry for this unit's source row
            int j = t64;
            float d0 = XS[j * 2]     - XS[i * 2];
            float d1 = XS[j * 2 + 1] - XS[i * 2 + 1];
            float r2 = d0 * d0 + d1 * d1;
            float rr = sqrtf(r2 + 1e-12f);
            *(float4*)(F4u + j * 4) = make_float4(d0, d1, rr, r2);
        }
        __syncthreads();
        {   // edge MLP hidden: thread owns column m
            int m = t64;
            float w0 = EW1[m], w1 = EW1[64 + m], w2 = EW1[128 + m], w3 = EW1[192 + m];
            float bb = BEB1[m];
            #pragma unroll 4
            for (int j = 0; j < 64; j++) {
                const float* f = F4u + j * 4;
                float v = fmaf(f[0], w0, fmaf(f[1], w1, fmaf(f[2], w2, fmaf(f[3], w3, bb))));
                T[j * 68 + m] = gelu_exact(v);
            }
        }
        __syncthreads();
        // hidden0 = gelu(edge_hidden @ W_A + bA + pre0[i])  [store to global]
        #pragma unroll
        for (int u = 0; u < 8; u++) badd[u] = PRE[il * 64 + mb + u] + BFA[mb + u];
        tile_gemm<0>(T, 68, WA, jb, mb, badd, T,
                     g_hid0 + (size_t)(b * 64 + i) * 4096, 0, -1);
        // gv0 = gelu(hidden0 @ W_B + bB), masked acc
        #pragma unroll
        for (int u = 0; u < 8; u++) badd[u] = BB[mb + u];
        tile_gemm<1>(T, 68, WB, jb, mb, badd, 0, 0, accR, i);
        __syncthreads();   // T reads done before next iq's edgeMLP writes
    }
    // combine unit accumulators -> g_accp[(b,half)]
    if (unit == 0) {
        float* T0 = sa + PA_T0;
        #pragma unroll
        for (int r = 0; r < 8; r++) {
            *(float4*)(T0 + (jb + r) * 68 + mb)     = make_float4(accR[r][0], accR[r][1], accR[r][2], accR[r][3]);
            *(float4*)(T0 + (jb + r) * 68 + mb + 4) = make_float4(accR[r][4], accR[r][5], accR[r][6], accR[r][7]);
        }
    }
    __syncthreads();
    if (unit == 1) {
        const float* T0 = sa + PA_T0;
        float* op = g_accp + (size_t)blockIdx.x * 4096;
        #pragma unroll
        for (int r = 0; r < 8; r++) {
            float4 p0 = *(const float4*)(T0 + (jb + r) * 68 + mb);
            float4 p1 = *(const float4*)(T0 + (jb + r) * 68 + mb + 4);
            *(float4*)(op + (jb + r) * 64 + mb) =
                make_float4(p0.x + accR[r][0], p0.y + accR[r][1], p0.z + accR[r][2], p0.w + accR[r][3]);
            *(float4*)(op + (jb + r) * 64 + mb + 4) =
                make_float4(p1.x + accR[r][4], p1.y + accR[r][5], p1.z + accR[r][6], p1.w + accR[r][7]);
        }
    }
}

// ---- pass B: hidden1 = gelu(hidden0 @ W_C + bC + pre1) -> gv1 (masked acc) ----
#define PB_T0   0        // 2 x [64][68]
#define PB_WC   8704
#define PB_WD   12800
#define PB_PRE  16896
#define PB_BFC  18944
#define PB_BD   19008
#define PB_FLOATS 19072
#define PB_BYTES (PB_FLOATS * 4)

__global__ void __launch_bounds__(128, 2)
k_passB()
{
    extern __shared__ float sb2[];
    const int tid = threadIdx.x;
    const int unit = tid >> 6, t64 = tid & 63;
    const int mb = (t64 & 7) * 8, jb = (t64 >> 3) * 8;
    const int b = blockIdx.x >> 1, half = blockIdx.x & 1;
    float* T   = sb2 + PB_T0 + unit * 4352;
    float* WC  = sb2 + PB_WC;
    float* WD  = sb2 + PB_WD;
    float* PRE = sb2 + PB_PRE;
    float* BFC = sb2 + PB_BFC;
    float* BD  = sb2 + PB_BD;

    for (int t = tid; t < 4096; t += 128) { WC[t] = g_Wf[8192 + t]; WD[t] = g_Wf[12288 + t]; }
    for (int t = tid; t < 2048; t += 128) PRE[t] = g_pre[b * 4096 + half * 2048 + t];
    if (tid < 64) { BFC[tid] = g_bf[128 + tid]; BD[tid] = g_bf[192 + tid]; }
    __syncthreads();

    float accR[8][8] = {};
    float badd[8];
    for (int iq = 0; iq < 16; iq++) {
        const int il = iq * 2 + unit;
        const int i = half * 32 + il;
        const float* Ab = g_hid0 + (size_t)(b * 64 + i) * 4096;
        #pragma unroll
        for (int u = 0; u < 8; u++) badd[u] = PRE[il * 64 + mb + u] + BFC[mb + u];
        tile_gemm<0>(Ab, 64, WC, jb, mb, badd, T, 0, 0, -1);
        #pragma unroll
        for (int u = 0; u < 8; u++) badd[u] = BD[mb + u];
        tile_gemm<1>(T, 68, WD, jb, mb, badd, 0, 0, accR, i);
    }
    __syncthreads();
    if (unit == 0) {
        float* T0 = sb2 + PB_T0;
        #pragma unroll
        for (int r = 0; r < 8; r++) {
            *(float4*)(T0 + (jb + r) * 68 + mb)     = make_float4(accR[r][0], accR[r][1], accR[r][2], accR[r][3]);
            *(float4*)(T0 + (jb + r) * 68 + mb + 4) = make_float4(accR[r][4], accR[r][5], accR[r][6], accR[r][7]);
        }
    }
    __syncthreads();
    if (unit == 1) {
        const float* T0 = sb2 + PB_T0;
        float* op = g_accp + (size_t)blockIdx.x * 4096;
        #pragma unroll
        for (int r = 0; r < 8; r++) {
            float4 p0 = *(const float4*)(T0 + (jb + r) * 68 + mb);
            float4 p1 = *(const float4*)(T0 + (jb + r) * 68 + mb + 4);
            *(float4*)(op + (jb + r) * 64 + mb) =
                make_float4(p0.x + accR[r][0], p0.y + accR[r][1], p0.z + accR[r][2], p0.w + accR[r][3]);
            *(float4*)(op + (jb + r) * 64 + mb + 4) =
                make_float4(p1.x + accR[r][4], p1.y + accR[r][5], p1.z + accR[r][6], p1.w + accR[r][7]);
        }
    }
}

// ---- node MLP: hv + pre(l=0) per batch ----
__global__ void __launch_bounds__(256)
k_node(const float* __restrict__ x, const float* __restrict__ spin,
       const float* __restrict__ nw1, const float* __restrict__ nb1,
       const float* __restrict__ nw2, const float* __restrict__ nb2,
       const float* __restrict__ vw1, const float* __restrict__ vb1)
{
    extern __shared__ float nsm[];
    float* sW = nsm; float* sA = nsm + 4096; float* sB = nsm + 8192;
    float* sb = nsm + 12288; float* sxs = nsm + 12352; float* ssp = nsm + 12480;
    float* sw1 = nsm + 12544; float* sb1 = nsm + 12736;
    const int b = blockIdx.x, tid = threadIdx.x;
    if (tid < 128) sxs[tid] = x[b * 128 + tid];
    if (tid < 64)  ssp[tid] = spin[b * 64 + tid];
    if (tid < 192) sw1[tid] = nw1[tid];
    if (tid < 64)  sb1[tid] = nb1[tid];
    for (int t = tid; t < 4096; t += 256) sW[t] = nw2[t];
    if (tid < 64) sb[tid] = nb2[tid];
    __syncthreads();
    for (int t = tid; t < 4096; t += 256) {
        int i = t >> 6, h = t & 63;
        float v = fmaf(sxs[i * 2], sw1[h],
                  fmaf(sxs[i * 2 + 1], sw1[64 + h],
                  fmaf(ssp[i], sw1[128 + h], sb1[h])));
        sA[t] = gelu_exact(v);
    }
    __syncthreads();
    mm64(sA, 64, sW, sb, sB, 64, 0, 1.f, false, tid);   // hv
    __syncthreads();
    for (int t = tid; t < 4096; t += 256) { g_hv[b * 4096 + t] = sB[t]; sW[t] = vw1[t]; }
    if (tid < 64) sb[tid] = vb1[tid];
    __syncthreads();
    mm64(sB, 64, sW, sb, sA, 64, 0, 1.f, false, tid);   // pre(l=0)
    __syncthreads();
    for (int t = tid; t < 4096; t += 256) g_pre[b * 4096 + t] = sA[t];
}

// ---- aggregate partials, hv update, pre for next layer ----
__global__ void __launch_bounds__(256)
k_agg(const float* __restrict__ ew2, const float* __restrict__ eb2,
      const float* __restrict__ vw1, const float* __restrict__ vb1, int l)
{
    extern __shared__ float gsm[];
    float* sA = gsm; float* sW = gsm + 4096; float* sH = gsm + 8192; float* sb = gsm + 12288;
    const int b = blockIdx.x, tid = threadIdx.x;
    for (int t = tid; t < 4096; t += 256) {
        sA[t] = g_accp[(size_t)(b * 2) * 4096 + t] + g_accp[(size_t)(b * 2 + 1) * 4096 + t];
        sW[t] = ew2[t];
        sH[t] = g_hv[b * 4096 + t];
    }
    if (tid < 64) sb[tid] = eb2[tid];
    __syncthreads();
    mm64(sA, 64, sW, sb, sH, 64, 0, 1.0f / 63.0f, true, tid);
    __syncthreads();
    for (int t = tid; t < 4096; t += 256) g_hv[b * 4096 + t] = sH[t];
    if (l == 0) {
        for (int t = tid; t < 4096; t += 256) sW[t] = vw1[t];
        if (tid < 64) sb[tid] = vb1[tid];
        __syncthreads();
        mm64(sH, 64, sW, sb, sA, 64, 0, 1.f, false, tid);
        __syncthreads();
        for (int t = tid; t < 4096; t += 256) g_pre[b * 4096 + t] = sA[t];
    }
}

// ---- head ----
__global__ void __launch_bounds__(256)
k_head(const float* __restrict__ hw1, const float* __restrict__ hb1,
       const float* __restrict__ hw2, const float* __restrict__ hb2,
       const float* __restrict__ scale, float* __restrict__ out)
{
    extern __shared__ float hsm[];
    float* sH = hsm; float* sW = hsm + 4096; float* sT = hsm + 8192;
    float* sb = hsm + 12288; float* sdx = hsm + 12352; float* smn = hsm + 12480;
    const int b = blockIdx.x, tid = threadIdx.x;
    for (int t = tid; t < 4096; t += 256) { sH[t] = g_hv[b * 4096 + t]; sW[t] = hw1[t]; }
    if (tid < 64) sb[tid] = hb1[tid];
    __syncthreads();
    mm64(sH, 64, sW, sb, sT, 64, 2, 1.f, false, tid);
    __syncthreads();
    if (tid < 128) {
        int j = tid >> 1, d = tid & 1;
        float sp = log1pf(expf(scale[0]));
        float s = hb2[d];
        const float* a = sT + j * 64;
        #pragma unroll
        for (int k = 0; k < 64; k++) s = fmaf(a[k], hw2[k * 2 + d], s);
        sdx[tid] = s * sp;
    }
    __syncthreads();
    if (tid < 2) {
        float s = 0.f;
        #pragma unroll
        for (int j = 0; j < 64; j++) s += sdx[j * 2 + tid];
        smn[tid] = s * (1.0f / 64.0f);
    }
    __syncthreads();
    if (tid < 128) out[b * 128 + tid] = sdx[tid] - smn[tid & 1];
}

extern "C" void kernel_launch(void* const* d_in, const int* in_sizes, int n_in,
                              void* d_out, int out_size) {
    (void)out_size;
    const float* ptr[23];
    bool dict_order = (n_in >= 23 && in_sizes[0] == 16384 && in_sizes[2] == 192);
    if (dict_order) {
        for (int i = 0; i < 23; i++) ptr[i] = (const float*)d_in[i];
    } else {
        static const int alpha_to_dict[23] = {
            15, 17, 14, 16,  7,  9,  6,  8, 19, 21, 18, 20,
             3,  5,  2,  4, 22,  1, 11, 13, 10, 12,  0
        };
        for (int i = 0; i < 23; i++) ptr[alpha_to_dict[i]] = (const float*)d_in[i];
    }
    float* out = (float*)d_out;

    const size_t SZ_NODE = 12800u * 4u;
    const size_t SZ_AGG  = 12352u * 4u;
    const size_t SZ_HEAD = 12482u * 4u;
    cudaFuncSetAttribute(k_passA, cudaFuncAttributeMaxDynamicSharedMemorySize, PA_BYTES);
    cudaFuncSetAttribute(k_passB, cudaFuncAttributeMaxDynamicSharedMemorySize, PB_BYTES);
    cudaFuncSetAttribute(k_node, cudaFuncAttributeMaxDynamicSharedMemorySize, (int)SZ_NODE);
    cudaFuncSetAttribute(k_agg,  cudaFuncAttributeMaxDynamicSharedMemorySize, (int)SZ_AGG);
    cudaFuncSetAttribute(k_head, cudaFuncAttributeMaxDynamicSharedMemorySize, (int)SZ_HEAD);

    // fused weight products W_A..W_D + bias rows
    k_wfuse<<<4, 256>>>(ptr[8], ptr[9], ptr[10], ptr[12], ptr[13], ptr[14], ptr[15]);
    // node MLP -> hv0, pre0
    k_node<<<128, 256, SZ_NODE>>>(ptr[0], ptr[1], ptr[2], ptr[3], ptr[4], ptr[5],
                                  ptr[10], ptr[11]);
    // pass A: hidden0 + gv0 accumulation
    k_passA<<<256, 128, PA_BYTES>>>(ptr[0], ptr[6], ptr[7]);
    // layer-0 aggregation -> hv1, pre1
    k_agg<<<128, 256, SZ_AGG>>>(ptr[16], ptr[17], ptr[10] + 8192, ptr[11] + 64, 0);
    // pass B: hidden1 + gv1 accumulation
    k_passB<<<256, 128, PB_BYTES>>>();
    // layer-1 aggregation -> hv2
    k_agg<<<128, 256, SZ_AGG>>>(ptr[16] + 4096, ptr[17] + 64, ptr[10] + 8192, ptr[11] + 64, 1);
    // head
    k_head<<<128, 256, SZ_HEAD>>>(ptr[18], ptr[19], ptr[20], ptr[21], ptr[22], out);
}